// round 9
// baseline (speedup 1.0000x reference)
#include <cuda_runtime.h>
#include <cuda_bf16.h>
#include <stdint.h>

#define Bq 4
#define Sq 2048
#define Eq 1024
#define Hq 16

#define SW128(o) ((o) ^ (((o) >> 3) & 0x70))
#define SW256(o) ((o) ^ (((o) >> 4) & 0x70))

// ---------------- scratch ----------------
__device__ float g_Q[Bq*Hq*Sq*64];
__device__ float g_K[Bq*Hq*Sq*64];
__device__ float g_V[Bq*Hq*Sq*64];
__device__ float g_ctx[(size_t)Bq*Sq*Eq];
__device__ float g_proj[(size_t)Bq*Sq*Eq];
__device__ float g_rowmax[Bq*Hq*Sq];
__device__ float g_rinv[Bq*Hq*Sq];
__device__ float2 g_pstat[(size_t)Bq*Hq*Sq*64];   // 64 partial (max,sumexp) per row

// ---------------- mma / ldmatrix helpers ----------------
__device__ __forceinline__ void ldsm4(uint32_t& r0, uint32_t& r1, uint32_t& r2, uint32_t& r3, uint32_t a) {
    asm volatile("ldmatrix.sync.aligned.m8n8.x4.shared.b16 {%0,%1,%2,%3},[%4];"
                 : "=r"(r0), "=r"(r1), "=r"(r2), "=r"(r3) : "r"(a));
}
__device__ __forceinline__ void ldsm2(uint32_t& r0, uint32_t& r1, uint32_t a) {
    asm volatile("ldmatrix.sync.aligned.m8n8.x2.shared.b16 {%0,%1},[%2];"
                 : "=r"(r0), "=r"(r1) : "r"(a));
}
__device__ __forceinline__ void ldsm2t(uint32_t& r0, uint32_t& r1, uint32_t a) {
    asm volatile("ldmatrix.sync.aligned.m8n8.x2.trans.shared.b16 {%0,%1},[%2];"
                 : "=r"(r0), "=r"(r1) : "r"(a));
}
__device__ __forceinline__ void mmab(float* c, const uint32_t* a, const uint32_t* b) {
    asm volatile("mma.sync.aligned.m16n8k16.row.col.f32.bf16.bf16.f32 "
                 "{%0,%1,%2,%3},{%4,%5,%6,%7},{%8,%9},{%0,%1,%2,%3};"
                 : "+f"(c[0]), "+f"(c[1]), "+f"(c[2]), "+f"(c[3])
                 : "r"(a[0]), "r"(a[1]), "r"(a[2]), "r"(a[3]), "r"(b[0]), "r"(b[1]));
}
__device__ __forceinline__ uint32_t smaddr(const void* p) {
    return (uint32_t)__cvta_generic_to_shared(p);
}
__device__ __forceinline__ void split4(float4 v, uint2& h, uint2& l) {
    __nv_bfloat16 h0 = __float2bfloat16(v.x), h1 = __float2bfloat16(v.y);
    __nv_bfloat16 h2 = __float2bfloat16(v.z), h3 = __float2bfloat16(v.w);
    __nv_bfloat16 l0 = __float2bfloat16(v.x - __bfloat162float(h0));
    __nv_bfloat16 l1 = __float2bfloat16(v.y - __bfloat162float(h1));
    __nv_bfloat16 l2 = __float2bfloat16(v.z - __bfloat162float(h2));
    __nv_bfloat16 l3 = __float2bfloat16(v.w - __bfloat162float(h3));
    __nv_bfloat162 ph0(h0, h1), ph1(h2, h3), pl0(l0, l1), pl1(l2, l3);
    h.x = *(uint32_t*)&ph0; h.y = *(uint32_t*)&ph1;
    l.x = *(uint32_t*)&pl0; l.y = *(uint32_t*)&pl1;
}

// ---------------- block reductions (ln kernel) ----------------
__device__ __forceinline__ float block_sum(float v) {
    __shared__ float sh[33];
    int lane = threadIdx.x & 31, w = threadIdx.x >> 5;
    #pragma unroll
    for (int o = 16; o; o >>= 1) v += __shfl_xor_sync(0xffffffffu, v, o);
    __syncthreads();
    if (lane == 0) sh[w] = v;
    __syncthreads();
    if (w == 0) {
        float x = (lane < 8) ? sh[lane] : 0.0f;
        #pragma unroll
        for (int o = 4; o; o >>= 1) x += __shfl_xor_sync(0xffffffffu, x, o);
        if (lane == 0) sh[32] = x;
    }
    __syncthreads();
    return sh[32];
}

// ---------------- projections / output GEMM, single 64KB buffer, 2 CTAs/SM ----------------
// mode = modeBase + blockIdx.z: 0/1/2 -> g_Q/g_K/g_V head layout; 3: g_ctx @ W0 -> g_proj
__global__ void __launch_bounds__(256, 2) gemm8192(const float* __restrict__ A0,
                                                   const float* __restrict__ A1,
                                                   const float* __restrict__ A2,
                                                   const float* __restrict__ W0,
                                                   const float* __restrict__ W1,
                                                   const float* __restrict__ W2,
                                                   int modeBase) {
    extern __shared__ char smraw[];
    int mode = modeBase + blockIdx.z;
    const float* Ap = (mode == 0) ? A0 : (mode == 1) ? A1 : (mode == 2) ? A2 : g_ctx;
    const float* W  = (mode == 1) ? W1 : (mode == 2) ? W2 : W0;
    int t = threadIdx.x, lane = t & 31, wid = t >> 5;
    int wm = wid >> 2, wn = wid & 3;                 // 2x4 warps, 64m x 32n each
    int m0 = blockIdx.y * 128, n0 = blockIdx.x * 128;
    int ar = t >> 4, ac4 = (t & 15) * 4;
    int bk = t >> 5, bc4 = (t & 31) * 4;
    char* Ah = smraw;
    char* Al = smraw + 16384;
    char* Bh = smraw + 32768;
    char* Bl = smraw + 49152;
    uint32_t sAh = smaddr(Ah), sAl = smaddr(Al), sBh = smaddr(Bh), sBl = smaddr(Bl);

    float4 pa[8], pb[8];
    float acc[4][4][4];
    #pragma unroll
    for (int i = 0; i < 4; i++)
        #pragma unroll
        for (int j = 0; j < 4; j++)
            #pragma unroll
            for (int e = 0; e < 4; e++) acc[i][j][e] = 0.0f;

    #pragma unroll
    for (int p = 0; p < 8; p++) {
        pa[p] = *(const float4*)&Ap[(size_t)(m0 + ar + 16 * p) * 1024 + ac4];
        pb[p] = *(const float4*)&W[(size_t)(bk + 8 * p) * 1024 + n0 + bc4];
    }

    for (int kt = 0; kt < 16; kt++) {
        if (kt) __syncthreads();       // previous MMA done before overwrite
        #pragma unroll
        for (int p = 0; p < 8; p++) {
            uint2 h, l;
            split4(pa[p], h, l);
            uint32_t off = SW128((ar + 16 * p) * 128 + ac4 * 2);
            *(uint2*)(Ah + off) = h; *(uint2*)(Al + off) = l;
            split4(pb[p], h, l);
            uint32_t offb = SW256((bk + 8 * p) * 256 + bc4 * 2);
            *(uint2*)(Bh + offb) = h; *(uint2*)(Bl + offb) = l;
        }
        __syncthreads();
        if (kt < 15) {
            #pragma unroll
            for (int p = 0; p < 8; p++) {
                pa[p] = *(const float4*)&Ap[(size_t)(m0 + ar + 16 * p) * 1024 + (kt + 1) * 64 + ac4];
                pb[p] = *(const float4*)&W[(size_t)((kt + 1) * 64 + bk + 8 * p) * 1024 + n0 + bc4];
            }
        }
        #pragma unroll
        for (int ks = 0; ks < 4; ks++) {
            uint32_t bhf[4][2], blf[4][2];
            #pragma unroll
            for (int in = 0; in < 4; in++) {
                int krow = ks * 16 + (lane & 15);
                int nb = (wn * 32 + in * 8) * 2;
                uint32_t off = SW256(krow * 256 + nb);
                ldsm2t(bhf[in][0], bhf[in][1], sBh + off);
                ldsm2t(blf[in][0], blf[in][1], sBl + off);
            }
            #pragma unroll
            for (int im = 0; im < 4; im++) {
                int arow = wm * 64 + im * 16 + (lane & 15);
                int acb = (ks * 16 + ((lane >> 4) << 3)) * 2;
                uint32_t off = SW128(arow * 128 + acb);
                uint32_t ah[4], al[4];
                ldsm4(ah[0], ah[1], ah[2], ah[3], sAh + off);
                ldsm4(al[0], al[1], al[2], al[3], sAl + off);
                #pragma unroll
                for (int in = 0; in < 4; in++) {
                    mmab(acc[im][in], ah, bhf[in]);
                    mmab(acc[im][in], al, bhf[in]);
                    mmab(acc[im][in], ah, blf[in]);
                }
            }
        }
    }

    int g = lane >> 2, c2 = (lane & 3) * 2;
    #pragma unroll
    for (int im = 0; im < 4; im++)
        #pragma unroll
        for (int in = 0; in < 4; in++)
            #pragma unroll
            for (int hh = 0; hh < 2; hh++) {
                int m = m0 + wm * 64 + im * 16 + g + hh * 8;
                int n = n0 + wn * 32 + in * 8 + c2;
                float2 v = make_float2(acc[im][in][hh * 2], acc[im][in][hh * 2 + 1]);
                if (mode <= 2) {
                    float* O = (mode == 0) ? g_Q : (mode == 1) ? g_K : g_V;
                    int b = m >> 11, s = m & 2047;
                    int h = n >> 6, d = n & 63;
                    *(float2*)&O[((size_t)(b * Hq + h) * Sq + s) * 64 + d] = v;
                } else {
                    *(float2*)&g_proj[(size_t)m * 1024 + n] = v;
                }
            }
}

// ---------------- scores: Q K^T (scaled+masked) -> attn, with partial row stats ----------------
__global__ void __launch_bounds__(256, 2) scores_kernel(const unsigned char* __restrict__ mask,
                                                        float* __restrict__ attn) {
    extern __shared__ char smraw[];
    char* Qh = smraw;                 // [128][64] SW128 bf16
    char* Ql = Qh + 16384;
    char* Kh = Ql + 16384;            // [128 kcol][64 d]
    char* Kl = Kh + 16384;
    int t = threadIdx.x, lane = t & 31, wid = t >> 5;
    int wm = wid >> 2, wn = wid & 3;
    int bh = blockIdx.z, q0 = blockIdx.y * 128, k0 = blockIdx.x * 128;
    size_t base = (size_t)bh * Sq * 64;
    uint32_t sQh = smaddr(Qh), sQl = smaddr(Ql), sKh = smaddr(Kh), sKl = smaddr(Kl);

    #pragma unroll
    for (int p = 0; p < 8; p++) {
        int r = (t >> 4) + 16 * p, c4 = (t & 15) * 4;
        uint32_t off = SW128(r * 128 + c4 * 2);
        float4 qv = *(const float4*)&g_Q[base + (size_t)(q0 + r) * 64 + c4];
        uint2 h, l; split4(qv, h, l);
        *(uint2*)(Qh + off) = h; *(uint2*)(Ql + off) = l;
        float4 kv = *(const float4*)&g_K[base + (size_t)(k0 + r) * 64 + c4];
        split4(kv, h, l);
        *(uint2*)(Kh + off) = h; *(uint2*)(Kl + off) = l;
    }
    __syncthreads();

    float acc[4][4][4];
    #pragma unroll
    for (int i = 0; i < 4; i++)
        #pragma unroll
        for (int j = 0; j < 4; j++)
            #pragma unroll
            for (int e = 0; e < 4; e++) acc[i][j][e] = 0.0f;

    #pragma unroll
    for (int ks = 0; ks < 4; ks++) {
        uint32_t bhf[4][2], blf[4][2];
        #pragma unroll
        for (int in = 0; in < 4; in++) {
            int nrow = wn * 32 + in * 8 + (lane & 7);
            int cb = (ks * 16 + (lane & 8)) * 2;
            uint32_t off = SW128(nrow * 128 + cb);
            ldsm2(bhf[in][0], bhf[in][1], sKh + off);
            ldsm2(blf[in][0], blf[in][1], sKl + off);
        }
        #pragma unroll
        for (int im = 0; im < 4; im++) {
            int arow = wm * 64 + im * 16 + (lane & 15);
            int acb = (ks * 16 + ((lane >> 4) << 3)) * 2;
            uint32_t off = SW128(arow * 128 + acb);
            uint32_t ah[4], al[4];
            ldsm4(ah[0], ah[1], ah[2], ah[3], sQh + off);
            ldsm4(al[0], al[1], al[2], al[3], sQl + off);
            #pragma unroll
            for (int in = 0; in < 4; in++) {
                mmab(acc[im][in], ah, bhf[in]);
                mmab(acc[im][in], al, bhf[in]);
                mmab(acc[im][in], ah, blf[in]);
            }
        }
    }

    int b = bh >> 4;
    int g = lane >> 2, c2 = (lane & 3) * 2;
    #pragma unroll
    for (int im = 0; im < 4; im++)
        #pragma unroll
        for (int hh = 0; hh < 2; hh++) {
            int q = q0 + wm * 64 + im * 16 + g + hh * 8;
            float vals[8];
            #pragma unroll
            for (int in = 0; in < 4; in++) {
                int kc = k0 + wn * 32 + in * 8 + c2;
                unsigned short mk = *(const unsigned short*)&mask[(size_t)b * Sq * Sq + (size_t)q * Sq + kc];
                float2 v;
                v.x = (mk & 0xffu) ? -1e9f : acc[im][in][hh * 2] * 0.125f;
                v.y = ((mk >> 8) & 0xffu) ? -1e9f : acc[im][in][hh * 2 + 1] * 0.125f;
                *(float2*)&attn[(size_t)bh * Sq * Sq + (size_t)q * Sq + kc] = v;
                vals[in * 2] = v.x; vals[in * 2 + 1] = v.y;
            }
            float m = vals[0];
            #pragma unroll
            for (int i = 1; i < 8; i++) m = fmaxf(m, vals[i]);
            m = fmaxf(m, __shfl_xor_sync(0xffffffffu, m, 1));
            m = fmaxf(m, __shfl_xor_sync(0xffffffffu, m, 2));
            float s = 0.0f;
            #pragma unroll
            for (int i = 0; i < 8; i++) s += __expf(vals[i] - m);
            s += __shfl_xor_sync(0xffffffffu, s, 1);
            s += __shfl_xor_sync(0xffffffffu, s, 2);
            if ((lane & 3) == 0)
                g_pstat[((size_t)bh * Sq + q) * 64 + blockIdx.x * 4 + wn] = make_float2(m, s);
        }
}

// ---------------- fold 64 partials per row -> rowmax, rinv ----------------
__global__ void __launch_bounds__(256) reduce_stats() {
    int r = blockIdx.x * 8 + (threadIdx.x >> 5);
    int lane = threadIdx.x & 31;
    float2 a = g_pstat[(size_t)r * 64 + lane];
    float2 b = g_pstat[(size_t)r * 64 + 32 + lane];
    float m = fmaxf(a.x, b.x);
    #pragma unroll
    for (int o = 16; o; o >>= 1) m = fmaxf(m, __shfl_xor_sync(0xffffffffu, m, o));
    float s = a.y * __expf(a.x - m) + b.y * __expf(b.x - m);
    #pragma unroll
    for (int o = 16; o; o >>= 1) s += __shfl_xor_sync(0xffffffffu, s, o);
    if (lane == 0) { g_rowmax[r] = m; g_rinv[r] = 1.0f / s; }
}

// ---------------- normalize attn + context = P @ V, single 48KB buffer, 2 CTAs/SM ----------------
__global__ void __launch_bounds__(256, 2) av_kernel(float* __restrict__ attn) {
    extern __shared__ char smraw[];
    int t = threadIdx.x, lane = t & 31, wid = t >> 5;
    int wm = wid >> 1, wn = wid & 1;            // 4x2 warps, 32q x 32n each
    int bh = blockIdx.y, q0 = blockIdx.x * 128;
    size_t abase = (size_t)bh * Sq * Sq;
    size_t vbase = (size_t)bh * Sq * 64;
    int r0 = bh * Sq + q0;
    int lr = t >> 4, c4 = (t & 15) * 4;
    char* Ph = smraw;
    char* Pl = smraw + 16384;
    char* Vh = smraw + 32768;
    char* Vl = smraw + 40960;
    uint32_t sPh = smaddr(Ph), sPl = smaddr(Pl), sVh = smaddr(Vh), sVl = smaddr(Vl);

    float mxv[8], riv[8];
    #pragma unroll
    for (int p = 0; p < 8; p++) {
        mxv[p] = g_rowmax[r0 + lr + 16 * p];
        riv[p] = g_rinv[r0 + lr + 16 * p];
    }

    float acc[2][4][4];
    #pragma unroll
    for (int i = 0; i < 2; i++)
        #pragma unroll
        for (int j = 0; j < 4; j++)
            #pragma unroll
            for (int e = 0; e < 4; e++) acc[i][j][e] = 0.0f;

    float4 sv[8], vv[4];
    #pragma unroll
    for (int p = 0; p < 8; p++)
        sv[p] = *(const float4*)&attn[abase + (size_t)(q0 + lr + 16 * p) * Sq + c4];
    #pragma unroll
    for (int p = 0; p < 4; p++)
        vv[p] = *(const float4*)&g_V[vbase + (size_t)(lr + 16 * p) * 64 + c4];

    for (int kt = 0; kt < 32; kt++) {
        if (kt) __syncthreads();       // previous MMA done before overwrite
        #pragma unroll
        for (int p = 0; p < 8; p++) {
            float4 pv;
            pv.x = __expf(sv[p].x - mxv[p]) * riv[p];
            pv.y = __expf(sv[p].y - mxv[p]) * riv[p];
            pv.z = __expf(sv[p].z - mxv[p]) * riv[p];
            pv.w = __expf(sv[p].w - mxv[p]) * riv[p];
            *(float4*)&attn[abase + (size_t)(q0 + lr + 16 * p) * Sq + kt * 64 + c4] = pv;
            uint2 h, l; split4(pv, h, l);
            uint32_t off = SW128((lr + 16 * p) * 128 + c4 * 2);
            *(uint2*)(Ph + off) = h; *(uint2*)(Pl + off) = l;
        }
        #pragma unroll
        for (int p = 0; p < 4; p++) {
            uint2 h, l; split4(vv[p], h, l);
            uint32_t off = SW128((lr + 16 * p) * 128 + c4 * 2);
            *(uint2*)(Vh + off) = h; *(uint2*)(Vl + off) = l;
        }
        __syncthreads();
        if (kt < 31) {
            #pragma unroll
            for (int p = 0; p < 8; p++)
                sv[p] = *(const float4*)&attn[abase + (size_t)(q0 + lr + 16 * p) * Sq + (kt + 1) * 64 + c4];
            #pragma unroll
            for (int p = 0; p < 4; p++)
                vv[p] = *(const float4*)&g_V[vbase + (size_t)((kt + 1) * 64 + lr + 16 * p) * 64 + c4];
        }
        #pragma unroll
        for (int ks = 0; ks < 4; ks++) {
            uint32_t bhf[4][2], blf[4][2];
            #pragma unroll
            for (int in = 0; in < 4; in++) {
                int krow = ks * 16 + (lane & 15);
                int nb = (wn * 32 + in * 8) * 2;
                uint32_t off = SW128(krow * 128 + nb);
                ldsm2t(bhf[in][0], bhf[in][1], sVh + off);
                ldsm2t(blf[in][0], blf[in][1], sVl + off);
            }
            #pragma unroll
            for (int im = 0; im < 2; im++) {
                int arow = wm * 32 + im * 16 + (lane & 15);
                int acb = (ks * 16 + ((lane >> 4) << 3)) * 2;
                uint32_t off = SW128(arow * 128 + acb);
                uint32_t ah[4], al[4];
                ldsm4(ah[0], ah[1], ah[2], ah[3], sPh + off);
                ldsm4(al[0], al[1], al[2], al[3], sPl + off);
                #pragma unroll
                for (int in = 0; in < 4; in++) {
                    mmab(acc[im][in], ah, bhf[in]);
                    mmab(acc[im][in], al, bhf[in]);
                    mmab(acc[im][in], ah, blf[in]);
                }
            }
        }
    }

    int b = bh >> 4, h = bh & 15;
    int g = lane >> 2, c2 = (lane & 3) * 2;
    #pragma unroll
    for (int im = 0; im < 2; im++)
        #pragma unroll
        for (int in = 0; in < 4; in++)
            #pragma unroll
            for (int hh = 0; hh < 2; hh++) {
                int q = q0 + wm * 32 + im * 16 + g + hh * 8;
                int n = wn * 32 + in * 8 + c2;
                float2 v = make_float2(acc[im][in][hh * 2], acc[im][in][hh * 2 + 1]);
                *(float2*)&g_ctx[(size_t)(b * Sq + q) * 1024 + h * 64 + n] = v;
            }
}

// ---------------- residual + LayerNorm ----------------
__global__ void __launch_bounds__(256) ln_kernel(const float* __restrict__ inQ,
                                                 const float* __restrict__ gamma,
                                                 const float* __restrict__ beta,
                                                 float* __restrict__ out) {
    int m = blockIdx.x, t = threadIdx.x;
    size_t base = (size_t)m * 1024;
    float x[4];
    float s = 0.0f;
    #pragma unroll
    for (int i = 0; i < 4; i++) {
        int c = i * 256 + t;
        x[i] = g_proj[base + c] + inQ[base + c];
        s += x[i];
    }
    s = block_sum(s);
    float mu = s * (1.0f / 1024.0f);
    float s2 = 0.0f;
    #pragma unroll
    for (int i = 0; i < 4; i++) { float d = x[i] - mu; s2 += d * d; }
    s2 = block_sum(s2);
    float rstd = rsqrtf(s2 * (1.0f / 1024.0f) + 1e-5f);
    #pragma unroll
    for (int i = 0; i < 4; i++) {
        int c = i * 256 + t;
        out[base + c] = (x[i] - mu) * rstd * gamma[c] + beta[c];
    }
}

// ---------------- launch ----------------
extern "C" void kernel_launch(void* const* d_in, const int* in_sizes, int n_in,
                              void* d_out, int out_size) {
    const float* inQ = (const float*)d_in[0];
    const float* inK = (const float*)d_in[1];
    const float* inV = (const float*)d_in[2];
    const unsigned char* mask = (const unsigned char*)d_in[3];
    const float* wQ = (const float*)d_in[4];
    const float* wK = (const float*)d_in[5];
    const float* wV = (const float*)d_in[6];
    const float* wO = (const float*)d_in[7];
    const float* gamma = (const float*)d_in[8];
    const float* beta = (const float*)d_in[9];
    float* out = (float*)d_out;
    float* attn = out + (size_t)Bq * Sq * Eq;

    const int GEMM_SMEM = 65536;   // single buffer, 2 CTAs/SM
    const int SC_SMEM   = 65536;
    const int AV_SMEM   = 49152;   // single buffer, 2 CTAs/SM
    cudaFuncSetAttribute(gemm8192, cudaFuncAttributeMaxDynamicSharedMemorySize, GEMM_SMEM);
    cudaFuncSetAttribute(scores_kernel, cudaFuncAttributeMaxDynamicSharedMemorySize, SC_SMEM);
    cudaFuncSetAttribute(av_kernel, cudaFuncAttributeMaxDynamicSharedMemorySize, AV_SMEM);

    dim3 blk(256);
    // fused Q/K/V projections: grid.z selects mode 0/1/2
    gemm8192<<<dim3(8, 64, 3), blk, GEMM_SMEM>>>(inQ, inK, inV, wQ, wK, wV, 0);
    scores_kernel<<<dim3(16, 16, 64), blk, SC_SMEM>>>(mask, attn);
    reduce_stats<<<Bq * Hq * Sq / 8, blk>>>();
    av_kernel<<<dim3(16, 64), blk, AV_SMEM>>>(attn);
    // output projection: mode 3 (W0 slot carries wO)
    gemm8192<<<dim3(8, 64, 1), blk, GEMM_SMEM>>>(nullptr, nullptr, nullptr, wO, nullptr, nullptr, 3);
    ln_kernel<<<Bq * Sq, blk>>>(inQ, gamma, beta, out);
}